// round 17
// baseline (speedup 1.0000x reference)
#include <cuda_runtime.h>
#include <math_constants.h>

#define BB   16
#define NN   2048
#define KNB  20
#define BN   (BB*NN)        // 32768
#define PTS  32
#define NBLK (BN/PTS)       // 1024
#define CCAT 512

// ---------------- scratch (device globals; no allocation allowed) ----------
__device__ int   g_idx [BN*KNB];
__device__ float g_hcat[BN*CCAT];
__device__ float g_pre [BN*256];
__device__ float g_part[NBLK*256*2];
__device__ float g_mean[256];
__device__ float g_rstd[256];

__global__ void nop_kernel() {}

// ---------------- kNN: EXACT top-20, two-pass (values then indices) --------
// Pass A keeps only the 20 largest VALUES via the min/max cascade
//   bv[j] = max(min(bv[j-1], v), bv[j])   (2 FMNMX/slot, exact)
// Pass B re-derives identical v (same FP ops) and collects indices:
// all v > thr, plus the first (by ascending m) eq_need with v == thr —
// matching jax.lax.top_k's stable tie rule. Consumers are set-invariant.
__global__ void __launch_bounds__(128) knn_kernel(const float* __restrict__ x)
{
    __shared__ float4 sp[NN];                // (x, y, z, |p|^2)
    const int b = blockIdx.y;
    const float* xb = x + (size_t)b*NN*3;
    for (int i = threadIdx.x; i < NN; i += 128) {
        float a0 = xb[i*3], a1 = xb[i*3+1], a2 = xb[i*3+2];
        sp[i] = make_float4(a0, a1, a2, a0*a0 + a1*a1 + a2*a2);
    }
    __syncthreads();
    const int n = blockIdx.x*128 + threadIdx.x;
    const float4 q = sp[n];

    // ---- Pass A: top-20 values only ----
    float bv[KNB];
    #pragma unroll
    for (int j = 0; j < KNB; ++j) bv[j] = -CUDART_INF_F;

    #pragma unroll 4
    for (int m = 0; m < NN; ++m) {
        float4 pm = sp[m];                   // broadcast LDS.128
        float v = 2.f*(q.x*pm.x + q.y*pm.y + q.z*pm.z) - q.w - pm.w;
        if (v > bv[KNB-1]) {
            #pragma unroll
            for (int j = KNB-1; j >= 1; --j)
                bv[j] = fmaxf(fminf(bv[j-1], v), bv[j]);
            bv[0] = fmaxf(bv[0], v);
        }
    }
    const float thr = bv[KNB-1];             // exact 20th-largest value
    int eq_need = 0;                         // #slots at the threshold
    #pragma unroll
    for (int j = 0; j < KNB; ++j) eq_need += (bv[j] == thr) ? 1 : 0;

    // ---- Pass B: collect indices (ascending m => earliest ties first) ----
    int* out = g_idx + ((size_t)b*NN + n)*KNB;
    int pos = 0;
    #pragma unroll 4
    for (int m = 0; m < NN; ++m) {
        float4 pm = sp[m];
        float v = 2.f*(q.x*pm.x + q.y*pm.y + q.z*pm.z) - q.w - pm.w;
        bool ts = v > thr;
        bool te = (v == thr) && (eq_need > 0);
        if (ts | te) {
            out[pos] = m;
            ++pos;
            if (te) --eq_need;
        }
    }
}

// ---------------- EdgeConv: pre-BN max over k + BN partials (128 threads) ---
__global__ void __launch_bounds__(128) edge_kernel(const float* __restrict__ x,
                                                   const float* __restrict__ w_edge)
{
    __shared__ float s_nb[PTS][KNB][3];
    __shared__ float s_ctr[PTS][3];
    __shared__ float xs[64], xs2[64];
    const int p0 = blockIdx.x * PTS;
    const int tid = threadIdx.x;

    for (int j = tid; j < PTS*KNB; j += 128) {
        int p = j / KNB, k = j - p*KNB;
        int gp = p0 + p;
        int bb = gp >> 11;
        int gi = g_idx[gp*KNB + k];
        const float* xp = x + ((size_t)bb*NN + gi)*3;
        s_nb[p][k][0] = xp[0]; s_nb[p][k][1] = xp[1]; s_nb[p][k][2] = xp[2];
    }
    if (tid < PTS) {
        int gp = p0 + tid;
        s_ctr[tid][0] = x[gp*3]; s_ctr[tid][1] = x[gp*3+1]; s_ctr[tid][2] = x[gp*3+2];
    }
    __syncthreads();

    const int o = tid & 63;
    const int sg = tid >> 6;                 // 0 or 1
    const float w0 = w_edge[o*6+0], w1 = w_edge[o*6+1], w2 = w_edge[o*6+2];
    const float w3 = w_edge[o*6+3], w4 = w_edge[o*6+4], w5 = w_edge[o*6+5];
    float s = 0.f, s2 = 0.f;
    const int pb = sg*16;
    for (int p = pb; p < pb+16; ++p) {
        float c0 = s_ctr[p][0], c1 = s_ctr[p][1], c2 = s_ctr[p][2];
        float base = w3*c0 + w4*c1 + w5*c2;
        float mx = -CUDART_INF_F;
        #pragma unroll
        for (int k = 0; k < KNB; ++k) {
            float v = base + w0*(s_nb[p][k][0]-c0)
                           + w1*(s_nb[p][k][1]-c1)
                           + w2*(s_nb[p][k][2]-c2);
            mx = fmaxf(mx, v);
            s += v; s2 += v*v;
        }
        g_pre[(size_t)(p0+p)*64 + o] = mx;
    }
    if (sg == 1) { xs[o] = s; xs2[o] = s2; }
    __syncthreads();
    if (sg == 0) {
        g_part[(size_t)blockIdx.x*128 + o*2]     = s  + xs[o];
        g_part[(size_t)blockIdx.x*128 + o*2 + 1] = s2 + xs2[o];
    }
}

// ---------------- BN statistics finalize (1 block per channel) --------------
__global__ void __launch_bounds__(256) stats_kernel(int O, float inv_count)
{
    __shared__ float rs[256], rs2[256];
    const int o = blockIdx.x;
    const int t = threadIdx.x;
    float s = 0.f, s2 = 0.f;
    for (int bk = t; bk < NBLK; bk += 256) {
        s  += g_part[(size_t)bk*O*2 + o*2];
        s2 += g_part[(size_t)bk*O*2 + o*2 + 1];
    }
    rs[t] = s; rs2[t] = s2;
    __syncthreads();
    for (int w = 128; w >= 1; w >>= 1) {
        if (t < w) { rs[t] += rs[t+w]; rs2[t] += rs2[t+w]; }
        __syncthreads();
    }
    if (t == 0) {
        float m   = rs[0]  * inv_count;
        float var = rs2[0] * inv_count - m*m;
        g_mean[o] = m;
        g_rstd[o] = rsqrtf(var + 1e-5f);
    }
}

// ---------------- BN + LeakyReLU apply (vectorized x4) ----------------------
__global__ void __launch_bounds__(256) apply_kernel(int O, int off)
{
    int i4 = blockIdx.x*256 + threadIdx.x;
    int i = i4*4;
    int p = i / O, o = i - p*O;
    float4 v = *reinterpret_cast<const float4*>(&g_pre[i]);
    v.x = (v.x - g_mean[o  ]) * g_rstd[o  ];
    v.y = (v.y - g_mean[o+1]) * g_rstd[o+1];
    v.z = (v.z - g_mean[o+2]) * g_rstd[o+2];
    v.w = (v.w - g_mean[o+3]) * g_rstd[o+3];
    v.x = v.x > 0.f ? v.x : 0.2f*v.x;
    v.y = v.y > 0.f ? v.y : 0.2f*v.y;
    v.z = v.z > 0.f ? v.z : 0.2f*v.z;
    v.w = v.w > 0.f ? v.w : 0.2f*v.w;
    *reinterpret_cast<float4*>(&g_hcat[(size_t)p*CCAT + off + o]) = v;
}

// ---------------- graph-max-pool gather + 1x1 conv + BN partials ------------
template<int CIN, int COUT>
__global__ void __launch_bounds__(128) layer_kernel(const float* __restrict__ w, int off_in)
{
    __shared__ float s_g[PTS*CIN];
    __shared__ int   s_idx[PTS*KNB];
    __shared__ float xs[128], xs2[128];
    const int tid = threadIdx.x;
    const int p0  = blockIdx.x * PTS;
    constexpr int C8 = CIN/8;

    for (int j = tid; j < PTS*KNB; j += 128) s_idx[j] = g_idx[(size_t)p0*KNB + j];
    __syncthreads();

    for (int v8 = tid; v8 < PTS*C8; v8 += 128) {
        int p = v8 / C8, c8 = (v8 - p*C8)*8;
        int gp = p0 + p, bb = gp >> 11;
        const float4* hb = reinterpret_cast<const float4*>(
            g_hcat + (size_t)bb*NN*CCAT + off_in + c8);
        float4 m0 = make_float4(-CUDART_INF_F,-CUDART_INF_F,-CUDART_INF_F,-CUDART_INF_F);
        float4 m1 = m0;
        #pragma unroll
        for (int j = 0; j < KNB; ++j) {
            size_t base = (size_t)s_idx[p*KNB+j]*(CCAT/4);
            float4 t0 = hb[base], t1 = hb[base+1];
            m0.x = fmaxf(m0.x, t0.x); m0.y = fmaxf(m0.y, t0.y);
            m0.z = fmaxf(m0.z, t0.z); m0.w = fmaxf(m0.w, t0.w);
            m1.x = fmaxf(m1.x, t1.x); m1.y = fmaxf(m1.y, t1.y);
            m1.z = fmaxf(m1.z, t1.z); m1.w = fmaxf(m1.w, t1.w);
        }
        *reinterpret_cast<float4*>(&s_g[p*CIN + c8])     = m0;
        *reinterpret_cast<float4*>(&s_g[p*CIN + c8 + 4]) = m1;
    }
    __syncthreads();

    constexpr int REP  = (COUT + 127)/128;
    constexpr int SEG  = (COUT >= 128) ? 1 : (128/COUT);
    constexpr int PSEG = PTS/SEG;
    const int o  = (COUT >= 128) ? tid : (tid & (COUT-1));
    const int sg = (COUT >= 128) ? 0   : (tid / COUT);
    const int pb = sg * PSEG;

    float acc[REP][PSEG];
    #pragma unroll
    for (int r = 0; r < REP; ++r)
        #pragma unroll
        for (int p = 0; p < PSEG; ++p) acc[r][p] = 0.f;

    for (int c = 0; c < CIN; ++c) {
        float wv[REP];
        #pragma unroll
        for (int r = 0; r < REP; ++r) wv[r] = w[(o + r*128)*CIN + c];
        #pragma unroll
        for (int p = 0; p < PSEG; ++p) {
            float sv = s_g[(pb + p)*CIN + c];
            #pragma unroll
            for (int r = 0; r < REP; ++r) acc[r][p] += wv[r]*sv;
        }
    }

    float s[REP], s2[REP];
    #pragma unroll
    for (int r = 0; r < REP; ++r) {
        s[r] = 0.f; s2[r] = 0.f;
        #pragma unroll
        for (int p = 0; p < PSEG; ++p) {
            float vv = acc[r][p];
            g_pre[(size_t)(p0 + pb + p)*COUT + o + r*128] = vv;
            s[r] += vv; s2[r] += vv*vv;
        }
    }
    if (SEG == 2) {
        if (sg == 1) { xs[o] = s[0]; xs2[o] = s2[0]; }
        __syncthreads();
        if (sg == 0) { s[0] += xs[o]; s2[0] += xs2[o]; }
    }
    if (sg == 0) {
        #pragma unroll
        for (int r = 0; r < REP; ++r) {
            g_part[(size_t)blockIdx.x*COUT*2 + (o + r*128)*2]     = s[r];
            g_part[(size_t)blockIdx.x*COUT*2 + (o + r*128)*2 + 1] = s2[r];
        }
    }
}

// ---------------- final 512->1024 GEMM (tf32 MMA, proven o64 single-buffer) -
__device__ __forceinline__ int fkey(float f) {
    int b = __float_as_int(f);
    return b >= 0 ? b : (b ^ 0x7FFFFFFF);
}

__global__ void out_init(int* ok) {
    ok[blockIdx.x*256 + threadIdx.x] = fkey(-CUDART_INF_F);
}

__device__ __forceinline__ unsigned cvt_tf32(float x) {
    unsigned u;
    asm("cvt.rna.tf32.f32 %0, %1;" : "=r"(u) : "f"(x));
    return u;
}

#define AST 36   // smem row stride (floats): frag loads conflict-free

__global__ void __launch_bounds__(256) final_kernel(const float* __restrict__ wf,
                                                    const float* __restrict__ bf,
                                                    int* __restrict__ okeys)
{
    __shared__ float sA[128*AST];   // [row][k] A tile 128x32 (tf32-rounded)
    __shared__ float sB[64*AST];    // [o]  [k] B tile 64x32
    __shared__ float sred[8][16];

    const int tid  = threadIdx.x;
    const int lane = tid & 31, w = tid >> 5;
    const int g = lane >> 2, tig = lane & 3;
    const int wm = w & 1, wn = w >> 1;           // warp tile: 64 rows x 16 cols
    const int b = blockIdx.z, n0 = blockIdx.x*128, o0 = blockIdx.y*64;
    const float* Ab = g_hcat + ((size_t)b*NN + n0)*CCAT;
    const float* Bw = wf + (size_t)o0*CCAT;

    float acc[4][2][4];
    #pragma unroll
    for (int mi = 0; mi < 4; ++mi)
        #pragma unroll
        for (int ni = 0; ni < 2; ++ni)
            #pragma unroll
            for (int j = 0; j < 4; ++j) acc[mi][ni][j] = 0.f;

    const int srow = tid >> 3;        // 0..31
    const int skq  = (tid & 7) * 4;   // 0,4,...,28

    for (int k0 = 0; k0 < CCAT; k0 += 32) {
        #pragma unroll
        for (int it = 0; it < 4; ++it) {
            int r = srow + it*32;
            float4 v = *reinterpret_cast<const float4*>(&Ab[(size_t)r*CCAT + k0 + skq]);
            float* d = &sA[r*AST + skq];
            d[0] = __uint_as_float(cvt_tf32(v.x));
            d[1] = __uint_as_float(cvt_tf32(v.y));
            d[2] = __uint_as_float(cvt_tf32(v.z));
            d[3] = __uint_as_float(cvt_tf32(v.w));
        }
        #pragma unroll
        for (int it = 0; it < 2; ++it) {
            int r = srow + it*32;
            float4 v = *reinterpret_cast<const float4*>(&Bw[(size_t)r*CCAT + k0 + skq]);
            float* d = &sB[r*AST + skq];
            d[0] = __uint_as_float(cvt_tf32(v.x));
            d[1] = __uint_as_float(cvt_tf32(v.y));
            d[2] = __uint_as_float(cvt_tf32(v.z));
            d[3] = __uint_as_float(cvt_tf32(v.w));
        }
        __syncthreads();

        #pragma unroll
        for (int k8 = 0; k8 < 4; ++k8) {
            const int kk = k8*8;
            unsigned a0[4], a1[4], a2[4], a3[4];
            #pragma unroll
            for (int mi = 0; mi < 4; ++mi) {
                int r = wm*64 + mi*16 + g;
                a0[mi] = __float_as_uint(sA[r*AST      + kk + tig]);
                a1[mi] = __float_as_uint(sA[(r+8)*AST  + kk + tig]);
                a2[mi] = __float_as_uint(sA[r*AST      + kk + tig + 4]);
                a3[mi] = __float_as_uint(sA[(r+8)*AST  + kk + tig + 4]);
            }
            unsigned b0[2], b1[2];
            #pragma unroll
            for (int ni = 0; ni < 2; ++ni) {
                int c = wn*16 + ni*8 + g;
                b0[ni] = __float_as_uint(sB[c*AST + kk + tig]);
                b1[ni] = __float_as_uint(sB[c*AST + kk + tig + 4]);
            }
            #pragma unroll
            for (int mi = 0; mi < 4; ++mi)
                #pragma unroll
                for (int ni = 0; ni < 2; ++ni) {
                    float* c = acc[mi][ni];
                    asm("mma.sync.aligned.m16n8k8.row.col.f32.tf32.tf32.f32 "
                        "{%0,%1,%2,%3}, {%4,%5,%6,%7}, {%8,%9}, {%0,%1,%2,%3};"
                        : "+f"(c[0]), "+f"(c[1]), "+f"(c[2]), "+f"(c[3])
                        : "r"(a0[mi]), "r"(a1[mi]), "r"(a2[mi]), "r"(a3[mi]),
                          "r"(b0[ni]), "r"(b1[ni]));
                }
        }
        __syncthreads();
    }

    #pragma unroll
    for (int ni = 0; ni < 2; ++ni) {
        float m0 = -CUDART_INF_F, m1 = -CUDART_INF_F;
        #pragma unroll
        for (int mi = 0; mi < 4; ++mi) {
            m0 = fmaxf(m0, fmaxf(acc[mi][ni][0], acc[mi][ni][2]));
            m1 = fmaxf(m1, fmaxf(acc[mi][ni][1], acc[mi][ni][3]));
        }
        #pragma unroll
        for (int sh = 4; sh <= 16; sh <<= 1) {
            m0 = fmaxf(m0, __shfl_xor_sync(0xffffffffu, m0, sh));
            m1 = fmaxf(m1, __shfl_xor_sync(0xffffffffu, m1, sh));
        }
        if (g == 0) {
            sred[w][ni*8 + tig*2]     = m0;
            sred[w][ni*8 + tig*2 + 1] = m1;
        }
    }
    __syncthreads();
    if (tid < 64) {
        int cwn = tid >> 4, c16 = tid & 15;
        float m = fmaxf(sred[cwn*2][c16], sred[cwn*2+1][c16]);
        int oc = o0 + cwn*16 + c16;
        m += bf[oc];                      // bias commutes with max over n
        atomicMax(&okeys[b*1024 + oc], fkey(m));
    }
}

__global__ void out_convert(int* ok, float* out) {
    int i = blockIdx.x*256 + threadIdx.x;
    int k = ok[i];
    int bits = k >= 0 ? k : (k ^ 0x7FFFFFFF);
    out[i] = __int_as_float(bits);
}

// ---------------- launch ----------------------------------------------------
extern "C" void kernel_launch(void* const* d_in, const int* in_sizes, int n_in,
                              void* d_out, int out_size)
{
    const float* x      = (const float*)d_in[0];
    const float* w_edge = (const float*)d_in[1];
    const float* w1     = (const float*)d_in[3];
    const float* w2     = (const float*)d_in[5];
    const float* w3     = (const float*)d_in[7];
    const float* wf     = (const float*)d_in[9];
    const float* bf     = (const float*)d_in[10];

    // slots 0-2 are fillers so the ncu capture (launch index 3) hits knn
    out_init<<<out_size/256, 256>>>((int*)d_out);
    nop_kernel<<<1, 32>>>();
    nop_kernel<<<1, 32>>>();

    knn_kernel<<<dim3(NN/128, BB), 128>>>(x);

    edge_kernel<<<NBLK, 128>>>(x, w_edge);
    stats_kernel<<<64, 256>>>(64, 1.f/(float)(BN*KNB));
    apply_kernel<<<BN*64/1024, 256>>>(64, 0);

    layer_kernel<64,64><<<NBLK, 128>>>(w1, 0);
    stats_kernel<<<64, 256>>>(64, 1.f/(float)BN);
    apply_kernel<<<BN*64/1024, 256>>>(64, 64);

    layer_kernel<64,128><<<NBLK, 128>>>(w2, 64);
    stats_kernel<<<128, 256>>>(128, 1.f/(float)BN);
    apply_kernel<<<BN*128/1024, 256>>>(128, 128);

    layer_kernel<128,256><<<NBLK, 128>>>(w3, 128);
    stats_kernel<<<256, 256>>>(256, 1.f/(float)BN);
    apply_kernel<<<BN*256/1024, 256>>>(256, 256);

    final_kernel<<<dim3(16, 16, 16), 256>>>(wf, bf, (int*)d_out);
    out_convert<<<out_size/256, 256>>>((int*)d_out, (float*)d_out);
}